// round 4
// baseline (speedup 1.0000x reference)
#include <cuda_runtime.h>
#include <math.h>
#include <stdint.h>

#define NN 20000
#define EE 320000
#define ITERS 10
#define MBK 157
#define FRAG 16384
#define NB 148
#define NTH 512

// ---------------- device scratch ----------------
__device__ float g_P0[NN * 256], g_P1[NN * 256], g_y[NN * 256];
__device__ float g_Ahi[MBK * FRAG], g_Alo[MBK * FRAG];   // h-frag (z0-frag during setup)
__device__ float g_Ghi[MBK * FRAG], g_Glo[MBK * FRAG];   // agg-frag (z1-frag during setup)
__device__ float g_a1[NN], g_a2[NN], g_mx[NN];
__device__ int   g_deg[NN], g_indptr[NN + 1], g_cursor[NN];
__device__ int   g_csr_src[EE], g_csr_eid[EE];
__device__ float g_B1f[98304];   // h-rows of [W1|W2], frag layout, K-ext split
__device__ float g_BPf[98304];   // z-rows of [W1|W2]
__device__ float g_B2f[49152];   // Wout
__device__ unsigned g_arrive;
__device__ unsigned g_ctr[32];

// ---------------- helpers ----------------
__device__ __forceinline__ float tf32_rd(float x) {
    uint32_t r;
    asm("cvt.rna.tf32.f32 %0, %1;" : "=r"(r) : "f"(x));
    return __uint_as_float(r);
}
__device__ __forceinline__ uint32_t smem_u32(const void* p) {
    uint32_t a;
    asm("{ .reg .u64 t; cvta.to.shared.u64 t, %1; cvt.u32.u64 %0, t; }" : "=r"(a) : "l"(p));
    return a;
}
__device__ __forceinline__ void cpasync16(uint32_t dst, const float* src) {
    asm volatile("cp.async.ca.shared.global [%0], [%1], 16;" :: "r"(dst), "l"(src));
}
__device__ __forceinline__ void mma_tf32(float* c, const uint32_t* a, const uint32_t* b) {
    asm volatile(
        "mma.sync.aligned.m16n8k8.row.col.f32.tf32.tf32.f32 "
        "{%0,%1,%2,%3}, {%4,%5,%6,%7}, {%8,%9}, {%0,%1,%2,%3};"
        : "+f"(c[0]), "+f"(c[1]), "+f"(c[2]), "+f"(c[3])
        : "r"(a[0]), "r"(a[1]), "r"(a[2]), "r"(a[3]), "r"(b[0]), "r"(b[1]));
}
__device__ __forceinline__ int fidx(int rv, int cc) {
    int ks = cc >> 5, kk = (cc >> 3) & 3, mtile = rv >> 4, r = rv & 15;
    return ks * 4096 + (mtile * 4 + kk) * 128 + ((r & 7) * 4 + (cc & 3)) * 4
         + (r >> 3) + (((cc >> 2) & 1) << 1);
}

// grid-wide barrier (epoch counting; all NB blocks resident)
__device__ __forceinline__ void gsync(unsigned& target) {
    __threadfence();
    __syncthreads();
    target += gridDim.x;
    if (threadIdx.x == 0) {
        atomicAdd(&g_arrive, 1u);
        unsigned v;
        do {
            asm volatile("ld.acquire.gpu.u32 %0, [%1];" : "=r"(v) : "l"(&g_arrive) : "memory");
        } while (v < target);
    }
    __syncthreads();
}

// ---------------- tf32-split GEMM tile (128 rows x 128 cols, K=384) ----------------
// MODE 0: store raw -> Cout (stride 256, col offset cb*128)   [P0/P1 setup]
// MODE 1: acc + P_sel(g_mx) -> g_y
// MODE 2: relu(acc+bias) -> h-frag (g_Ahi/g_Alo) + fused decoder gemv -> g_a1/g_a2
template <int MODE>
__device__ __forceinline__ void gemm_tile(
    float* smem, int mb, int cb,
    const float* __restrict__ Ahi, const float* __restrict__ Alo,
    const float* __restrict__ Bf, float* __restrict__ Cout,
    const float* __restrict__ bias, const float* __restrict__ Wdec)
{
    const int tid = threadIdx.x, lane = tid & 31, wid = tid >> 5;
    const int wm = wid & 3, wn = wid >> 2;
    const uint32_t sbase = smem_u32(smem);
    float acc[2][4][4];
#pragma unroll
    for (int i = 0; i < 2; i++)
#pragma unroll
        for (int j = 0; j < 4; j++)
#pragma unroll
            for (int q = 0; q < 4; q++) acc[i][j][q] = 0.0f;
    const float* Bcb = Bf + cb * 49152;

    auto stage = [&](int st, int buf) {
        const float* As = (((st >> 2) == 1) ? Alo : Ahi) + mb * FRAG + (st & 3) * 4096;
        const float* Bs = Bcb + st * 4096;
        uint32_t da = sbase + buf * 32768;
        uint32_t db = da + 16384;
#pragma unroll
        for (int i = 0; i < 2; i++) {
            int f = tid + NTH * i;
            cpasync16(da + f * 16, As + f * 4);
            cpasync16(db + f * 16, Bs + f * 4);
        }
    };

    stage(0, 0);
    asm volatile("cp.async.commit_group;");
    for (int c = 0; c < 12; c++) {
        int buf = c & 1;
        if (c < 11) {
            stage(c + 1, buf ^ 1);
            asm volatile("cp.async.commit_group;");
            asm volatile("cp.async.wait_group 1;");
        } else {
            asm volatile("cp.async.wait_group 0;");
        }
        __syncthreads();
        const uint4* Ab = (const uint4*)(smem + buf * 8192);
        const uint2* Bb = (const uint2*)(smem + buf * 8192 + 4096);
#pragma unroll
        for (int kk = 0; kk < 4; kk++) {
            uint4 a[2];
            uint2 b[4];
#pragma unroll
            for (int mt = 0; mt < 2; mt++) a[mt] = Ab[((wm * 2 + mt) * 4 + kk) * 32 + lane];
#pragma unroll
            for (int nt = 0; nt < 4; nt++) b[nt] = Bb[((wn * 4 + nt) * 4 + kk) * 32 + lane];
#pragma unroll
            for (int mt = 0; mt < 2; mt++)
#pragma unroll
                for (int nt = 0; nt < 4; nt++)
                    mma_tf32(acc[mt][nt], (const uint32_t*)&a[mt], (const uint32_t*)&b[nt]);
        }
        __syncthreads();
    }

    const int row0 = mb * 128, colofs = cb * 128;
    float s1r[4], s2r[4];
#pragma unroll
    for (int i = 0; i < 4; i++) { s1r[i] = 0.0f; s2r[i] = 0.0f; }

#pragma unroll
    for (int mt = 0; mt < 2; mt++) {
        int rva = wm * 32 + mt * 16 + (lane >> 2);
        int rvb = rva + 8;
        int ga = row0 + rva, gb = row0 + rvb;
        const float *Pa = nullptr, *Pb = nullptr;
        if (MODE == 1) {
            if (ga < NN) Pa = (g_mx[ga] >= 0.4f) ? g_P1 : g_P0;
            if (gb < NN) Pb = (g_mx[gb] >= 0.4f) ? g_P1 : g_P0;
        }
#pragma unroll
        for (int nt = 0; nt < 4; nt++) {
            int col = wn * 32 + nt * 8 + ((lane & 3) << 1);
            float c0 = acc[mt][nt][0], c1 = acc[mt][nt][1];
            float c2 = acc[mt][nt][2], c3 = acc[mt][nt][3];
            if (MODE == 0) {
                if (ga < NN) { float2 v = {c0, c1}; *(float2*)(Cout + (size_t)ga * 256 + colofs + col) = v; }
                if (gb < NN) { float2 v = {c2, c3}; *(float2*)(Cout + (size_t)gb * 256 + colofs + col) = v; }
            } else if (MODE == 1) {
                if (ga < NN) {
                    float2 pv = *(const float2*)(Pa + (size_t)ga * 256 + colofs + col);
                    float2 v = {c0 + pv.x, c1 + pv.y};
                    *(float2*)(g_y + (size_t)ga * 256 + colofs + col) = v;
                }
                if (gb < NN) {
                    float2 pv = *(const float2*)(Pb + (size_t)gb * 256 + colofs + col);
                    float2 v = {c2 + pv.x, c3 + pv.y};
                    *(float2*)(g_y + (size_t)gb * 256 + colofs + col) = v;
                }
            } else {
                float b0 = bias[col], b1 = bias[col + 1];
                float w10 = Wdec[col], w11 = Wdec[col + 1];
                float w20 = Wdec[128 + col], w21 = Wdec[128 + col + 1];
                float v0 = fmaxf(c0 + b0, 0.0f), v1 = fmaxf(c1 + b1, 0.0f);
                float v2 = fmaxf(c2 + b0, 0.0f), v3 = fmaxf(c3 + b1, 0.0f);
                s1r[mt * 2 + 0] += v0 * w10 + v1 * w11;
                s2r[mt * 2 + 0] += v0 * w20 + v1 * w21;
                s1r[mt * 2 + 1] += v2 * w10 + v3 * w11;
                s2r[mt * 2 + 1] += v2 * w20 + v3 * w21;
                if (ga < NN) {
                    int i0 = mb * FRAG + fidx(rva, col), i1 = mb * FRAG + fidx(rva, col + 1);
                    float h0 = tf32_rd(v0); g_Ahi[i0] = h0; g_Alo[i0] = tf32_rd(v0 - h0);
                    float h1 = tf32_rd(v1); g_Ahi[i1] = h1; g_Alo[i1] = tf32_rd(v1 - h1);
                }
                if (gb < NN) {
                    int i0 = mb * FRAG + fidx(rvb, col), i1 = mb * FRAG + fidx(rvb, col + 1);
                    float h0 = tf32_rd(v2); g_Ahi[i0] = h0; g_Alo[i0] = tf32_rd(v2 - h0);
                    float h1 = tf32_rd(v3); g_Ahi[i1] = h1; g_Alo[i1] = tf32_rd(v3 - h1);
                }
            }
        }
    }
    if (MODE == 2) {
        // deterministic fused gemv: 16 partial slots per row, fixed-order reduce
        float* red = smem;  // 128*16*2 floats = 16KB (buffer 0 region, mainloop done)
#pragma unroll
        for (int mt = 0; mt < 2; mt++)
#pragma unroll
            for (int hf = 0; hf < 2; hf++) {
                int rl = wm * 32 + mt * 16 + (lane >> 2) + hf * 8;
                red[rl * 16 + wn * 4 + (lane & 3)] = s1r[mt * 2 + hf];
                red[2048 + rl * 16 + wn * 4 + (lane & 3)] = s2r[mt * 2 + hf];
            }
        __syncthreads();
        if (tid < 128) {
            int ga = row0 + tid;
            if (ga < NN) {
                float a = 0.0f, b = 0.0f;
#pragma unroll
                for (int q = 0; q < 16; q++) { a += red[tid * 16 + q]; b += red[2048 + tid * 16 + q]; }
                g_a1[ga] = a;
                g_a2[ga] = b;
            }
        }
        __syncthreads();
    }
}

// ---------------- setup kernels ----------------
__global__ void k_init() {
    int t = blockIdx.x * blockDim.x + threadIdx.x;
    if (t < NN) { g_deg[t] = 0; g_mx[t] = 0.0f; }
    if (t < 32) g_ctr[t] = 0;
    if (t == 32) g_arrive = 0;
}
__global__ void k_hist(const int* __restrict__ ei) {
    int e = blockIdx.x * blockDim.x + threadIdx.x;
    if (e < EE) atomicAdd(&g_deg[ei[EE + e]], 1);
}
__global__ void k_scan() {
    __shared__ int sh[1024];
    int t = threadIdx.x;
    const int CH = 20;
    int base = t * CH, s = 0;
    for (int i = 0; i < CH; i++) { int idx = base + i; if (idx < NN) s += g_deg[idx]; }
    sh[t] = s;
    __syncthreads();
    for (int o = 1; o < 1024; o <<= 1) {
        int v = (t >= o) ? sh[t - o] : 0;
        __syncthreads();
        sh[t] += v;
        __syncthreads();
    }
    int run = (t == 0) ? 0 : sh[t - 1];
    for (int i = 0; i < CH; i++) {
        int idx = base + i;
        if (idx < NN) { g_indptr[idx] = run; g_cursor[idx] = run; run += g_deg[idx]; }
    }
    if (t == 1023) g_indptr[NN] = sh[1023];
}
// fused: CSR scatter + B-table packing + z0/z1 frag prep
__global__ void k_fused(const int* __restrict__ ei,
                        const float* __restrict__ W1, const float* __restrict__ W2,
                        const float* __restrict__ Wout,
                        const float* __restrict__ pos, const float* __restrict__ Wenc,
                        const float* __restrict__ benc) {
    int t0 = blockIdx.x * blockDim.x + threadIdx.x;
    int gs = gridDim.x * blockDim.x;
    for (int e = t0; e < EE; e += gs) {
        int d = ei[EE + e];
        int slot = atomicAdd(&g_cursor[d], 1);
        g_csr_src[slot] = ei[e];
        g_csr_eid[slot] = e;
    }
    for (int t = t0; t < 245760; t += gs) {
        int which, rem;
        if (t < 98304) { which = 0; rem = t; }
        else if (t < 196608) { which = 1; rem = t - 98304; }
        else { which = 2; rem = t - 196608; }
        int cb = rem / 49152;
        int r2 = rem % 49152;
        int ks = r2 >> 12;
        int r3 = r2 & 4095;
        int ntile = r3 >> 8;
        int r4 = r3 & 255;
        int kk = r4 >> 6;
        int r5 = r4 & 63;
        int lane = r5 >> 1, slot = r5 & 1;
        int n = cb * 128 + ntile * 8 + (lane >> 2);
        int ke = ks * 32 + kk * 8 + slot * 4 + (lane & 3);
        int k = ke & 127;
        float v;
        if (which == 0)      v = (n < 128) ? W1[(128 + k) * 128 + n] : W2[(128 + k) * 128 + (n - 128)];
        else if (which == 1) v = (n < 128) ? W1[k * 128 + n] : W2[k * 128 + (n - 128)];
        else                 v = Wout[k * 128 + n];
        float hi = tf32_rd(v);
        float o = (ke < 256) ? hi : tf32_rd(v - hi);
        if (which == 0) g_B1f[rem] = o;
        else if (which == 1) g_BPf[rem] = o;
        else g_B2f[rem] = o;
    }
    for (int t = t0; t < NN * 32; t += gs) {
        int v = t >> 5, c0 = (t & 31) << 2;
        float p = pos[v];
        float4 w0 = *(const float4*)(Wenc + c0);
        float4 w1 = *(const float4*)(Wenc + 128 + c0);
        float4 b = *(const float4*)(benc + c0);
        int base = (v >> 7) * FRAG;
        int rvb = v & 127;
#pragma unroll
        for (int rv = 0; rv < 2; rv++) {
            float rr = (float)rv;
            float z[4];
            z[0] = fmaxf(fmaf(p, w0.x, fmaf(rr, w1.x, b.x)), 0.0f);
            z[1] = fmaxf(fmaf(p, w0.y, fmaf(rr, w1.y, b.y)), 0.0f);
            z[2] = fmaxf(fmaf(p, w0.z, fmaf(rr, w1.z, b.z)), 0.0f);
            z[3] = fmaxf(fmaf(p, w0.w, fmaf(rr, w1.w, b.w)), 0.0f);
            float* dhi = rv ? g_Ghi : g_Ahi;
            float* dlo = rv ? g_Glo : g_Alo;
#pragma unroll
            for (int q = 0; q < 4; q++) {
                float hi = tf32_rd(z[q]);
                int idx = base + fidx(rvb, c0 + q);
                dhi[idx] = hi;
                dlo[idx] = tf32_rd(z[q] - hi);
            }
        }
    }
}
// one launch computes both P0 (blocks 0..313, A=z0-frag) and P1 (blocks 314..627, A=z1-frag)
__global__ __launch_bounds__(NTH, 1) void k_setupgemm() {
    extern __shared__ float smem[];
    int b = blockIdx.x;
    if (b < 2 * MBK)
        gemm_tile<0>(smem, b >> 1, b & 1, g_Ahi, g_Alo, g_BPf, g_P0, nullptr, nullptr);
    else {
        b -= 2 * MBK;
        gemm_tile<0>(smem, b >> 1, b & 1, g_Ghi, g_Glo, g_BPf, g_P1, nullptr, nullptr);
    }
}

// ---------------- persistent iteration kernel ----------------
__global__ __launch_bounds__(NTH, 1) void k_persist(
    const float* __restrict__ s, const int* __restrict__ ei,
    const float* __restrict__ bmsg, const float* __restrict__ bout,
    const float* __restrict__ Wdec, const float* __restrict__ bdec,
    float* __restrict__ out)
{
    extern __shared__ float smem[];
    __shared__ int s_tile;
    const int tid = threadIdx.x, lane = tid & 31, wid = tid >> 5;
    const int wg = blockIdx.x * (NTH / 32) + wid;
    const int nwg = gridDim.x * (NTH / 32);
    const int gstride = gridDim.x * NTH;
    unsigned target = 0;
    const float bd = bdec[0];

    for (int it = 0; it < ITERS; it++) {
        // ---- Phase A: y = h@[W1h|W2h] + P_sel (it==0: y = P_sel, h==0) ----
        if (it == 0) {
            for (int idx = blockIdx.x * NTH + tid; idx < NN * 64; idx += gstride) {
                int v = idx >> 6, q = (idx & 63) << 2;
                const float* P = (s[v] > 0.5f) ? g_P1 : g_P0;
                *(float4*)(g_y + (size_t)v * 256 + q) = *(const float4*)(P + (size_t)v * 256 + q);
            }
        } else {
            unsigned* ctr = &g_ctr[it];
            for (;;) {
                __syncthreads();
                if (tid == 0) s_tile = (int)atomicAdd(ctr, 1u);
                __syncthreads();
                int t = s_tile;
                if (t >= 2 * MBK) break;
                gemm_tile<1>(smem, t >> 1, t & 1, g_Ahi, g_Alo, g_B1f, nullptr, nullptr, nullptr);
            }
        }
        gsync(target);

        // ---- Phase B: per-dst segment max + agg-frag split (+ mx zero) ----
        for (int u = wg; u < NN * 2; u += nwg) {
            int w = u >> 1, hf = u & 1;
            int beg = g_indptr[w], end = g_indptr[w + 1];
            int c0 = hf * 64 + lane * 2;
            float m0 = -INFINITY, m1 = -INFINITY;
            for (int j = beg; j < end; j++) {
                int sv = g_csr_src[j];
                float2 v = *(const float2*)(g_y + (size_t)sv * 256 + c0);
                m0 = fmaxf(m0, v.x);
                m1 = fmaxf(m1, v.y);
            }
            float o0, o1;
            if (end > beg) {
                float2 y2 = *(const float2*)(g_y + (size_t)w * 256 + 128 + c0);
                float2 b = *(const float2*)(bmsg + c0);
                o0 = fmaxf(m0 + y2.x + b.x, 0.0f);
                o1 = fmaxf(m1 + y2.y + b.y, 0.0f);
            } else { o0 = 0.0f; o1 = 0.0f; }
            int base = (w >> 7) * FRAG;
            int i0 = base + fidx(w & 127, c0), i1 = base + fidx(w & 127, c0 + 1);
            float h0 = tf32_rd(o0); g_Ghi[i0] = h0; g_Glo[i0] = tf32_rd(o0 - h0);
            float h1 = tf32_rd(o1); g_Ghi[i1] = h1; g_Glo[i1] = tf32_rd(o1 - h1);
            if (hf == 0 && lane == 0) g_mx[w] = 0.0f;
        }
        gsync(target);

        // ---- Phase C: h = relu(agg@Wout + b) -> h-frag + fused decoder gemv ----
        {
            unsigned* ctr = &g_ctr[16 + it];
            for (;;) {
                __syncthreads();
                if (tid == 0) s_tile = (int)atomicAdd(ctr, 1u);
                __syncthreads();
                int t = s_tile;
                if (t >= MBK) break;
                gemm_tile<2>(smem, t, 0, g_Ghi, g_Glo, g_B2f, nullptr, bout, Wdec);
            }
        }
        gsync(target);

        // ---- Phase E: alpha per edge + incident max ----
        for (int e = blockIdx.x * NTH + tid; e < EE; e += gstride) {
            int sv = ei[e], dv = ei[EE + e];
            float t = g_a1[sv] + g_a2[dv] + bd;
            float al = 1.0f / (1.0f + expf(-t));
            out[(size_t)it * EE + e] = al;
            atomicMax((int*)&g_mx[sv], __float_as_int(al));
            atomicMax((int*)&g_mx[dv], __float_as_int(al));
        }
        gsync(target);
    }

    // ---- Final: reach + parents ----
    for (int w = wg; w < NN; w += nwg) {
        if (lane == 0) out[(size_t)10 * EE + w] = (g_mx[w] >= 0.4f) ? 1.0f : 0.0f;
        int beg = g_indptr[w], end = g_indptr[w + 1];
        float a2v = g_a2[w];
        float ba = -1.0f;
        int beid = 0x7FFFFFFF, bsrc = w;
        for (int j = beg + lane; j < end; j += 32) {
            int sv = g_csr_src[j], eid = g_csr_eid[j];
            float t = g_a1[sv] + a2v + bd;
            float al = 1.0f / (1.0f + expf(-t));
            if (al > ba || (al == ba && eid < beid)) { ba = al; beid = eid; bsrc = sv; }
        }
#pragma unroll
        for (int o = 16; o; o >>= 1) {
            float oa = __shfl_xor_sync(0xFFFFFFFFu, ba, o);
            int oe = __shfl_xor_sync(0xFFFFFFFFu, beid, o);
            int os = __shfl_xor_sync(0xFFFFFFFFu, bsrc, o);
            if (oa > ba || (oa == ba && oe < beid)) { ba = oa; beid = oe; bsrc = os; }
        }
        if (lane == 0) out[(size_t)10 * EE + NN + w] = (float)((end > beg) ? bsrc : w);
    }
}

// ---------------- host ----------------
extern "C" void kernel_launch(void* const* d_in, const int* in_sizes, int n_in,
                              void* d_out, int out_size) {
    const float* pos  = (const float*)d_in[0];
    const float* s    = (const float*)d_in[1];
    const int*   ei   = (const int*)d_in[2];
    const float* Wenc = (const float*)d_in[3];
    const float* benc = (const float*)d_in[4];
    const float* W1   = (const float*)d_in[5];
    const float* W2   = (const float*)d_in[6];
    const float* bmsg = (const float*)d_in[7];
    const float* Wout = (const float*)d_in[8];
    const float* bout = (const float*)d_in[9];
    const float* Wdec = (const float*)d_in[10];
    const float* bdec = (const float*)d_in[11];
    float* out = (float*)d_out;

    const int SMEM = 65536;
    cudaFuncSetAttribute(k_setupgemm, cudaFuncAttributeMaxDynamicSharedMemorySize, SMEM);
    cudaFuncSetAttribute(k_persist, cudaFuncAttributeMaxDynamicSharedMemorySize, SMEM);

    const int TB = 256;
    k_init<<<(NN + TB - 1) / TB, TB>>>();                                   // 0
    k_hist<<<(EE + TB - 1) / TB, TB>>>(ei);                                 // 1
    k_scan<<<1, 1024>>>();                                                  // 2
    k_fused<<<1024, TB>>>(ei, W1, W2, Wout, pos, Wenc, benc);               // 3
    k_setupgemm<<<4 * MBK, NTH, SMEM>>>();                                  // 4
    k_persist<<<NB, NTH, SMEM>>>(s, ei, bmsg, bout, Wdec, bdec, out);       // 5 (ncu -s 5)
}

// round 5
// speedup vs baseline: 1.8115x; 1.8115x over previous
#include <cuda_runtime.h>
#include <cuda_fp16.h>
#include <math.h>
#include <stdint.h>

#define NN 20000
#define EE 320000
#define ITERS 10
#define MBK 157
#define FRAGH 8192   // u32 words per 128x128 fp16 A-fragment block

// ---------------- device scratch ----------------
__device__ float g_P0[NN * 256], g_P1[NN * 256], g_y[NN * 256];
__device__ uint32_t g_Ahf[MBK * FRAGH], g_Alf[MBK * FRAGH];  // h hi/lo frag (z0 during setup)
__device__ uint32_t g_Ghf[MBK * FRAGH], g_Glf[MBK * FRAGH];  // agg hi/lo frag (z1 during setup)
__device__ float g_a1[NN], g_a2[NN], g_mx[NN];
__device__ int   g_deg[NN], g_indptr[NN + 1], g_cursor[NN];
__device__ int   g_csr_src[EE], g_csr_eid[EE];
__device__ uint32_t g_B1h[2 * 24576];  // h-rows of [W1|W2], frag layout, 24 ksteps (hi,hi,lo)
__device__ uint32_t g_BPh[2 * 24576];  // z-rows of [W1|W2]
__device__ uint32_t g_B2h[24576];      // Wout

// ---------------- helpers ----------------
__device__ __forceinline__ uint32_t smem_u32(const void* p) {
    uint32_t a;
    asm("{ .reg .u64 t; cvta.to.shared.u64 t, %1; cvt.u32.u64 %0, t; }" : "=r"(a) : "l"(p));
    return a;
}
__device__ __forceinline__ void cpasync16(uint32_t dst, const void* src) {
    asm volatile("cp.async.ca.shared.global [%0], [%1], 16;" :: "r"(dst), "l"(src));
}
__device__ __forceinline__ uint32_t pk2h(float a, float b) {
    __half2 h = __floats2half2_rn(a, b);
    return *(uint32_t*)&h;
}
__device__ __forceinline__ float hi16(float v) { return __half2float(__float2half_rn(v)); }
__device__ __forceinline__ void mma_f16(float* c, const uint32_t* a, const uint32_t* b) {
    asm volatile(
        "mma.sync.aligned.m16n8k16.row.col.f32.f16.f16.f32 "
        "{%0,%1,%2,%3}, {%4,%5,%6,%7}, {%8,%9}, {%0,%1,%2,%3};"
        : "+f"(c[0]), "+f"(c[1]), "+f"(c[2]), "+f"(c[3])
        : "r"(a[0]), "r"(a[1]), "r"(a[2]), "r"(a[3]), "r"(b[0]), "r"(b[1]));
}
// word index of (row rv in [0,128), even col cc in [0,128)) inside one A-frag block
__device__ __forceinline__ int fidxh(int rv, int cc) {
    int ks = cc >> 4, kk = cc & 15, mt = rv >> 4, r = rv & 15;
    int slot = (r >> 3) + ((kk >> 3) << 1);
    int lane = ((r & 7) << 2) | ((kk & 7) >> 1);
    return ((ks * 8 + mt) * 32 + lane) * 4 + slot;
}

// ---------------- setup kernels ----------------
__global__ void k_init() {
    int t = blockIdx.x * blockDim.x + threadIdx.x;
    if (t < NN) { g_deg[t] = 0; g_mx[t] = 0.0f; }
}
__global__ void k_hist(const int* __restrict__ ei) {
    int e = blockIdx.x * blockDim.x + threadIdx.x;
    if (e < EE) atomicAdd(&g_deg[ei[EE + e]], 1);
}
__global__ void k_scan() {
    __shared__ int sh[1024];
    int t = threadIdx.x;
    const int CH = 20;
    int base = t * CH, s = 0;
    for (int i = 0; i < CH; i++) { int idx = base + i; if (idx < NN) s += g_deg[idx]; }
    sh[t] = s;
    __syncthreads();
    for (int o = 1; o < 1024; o <<= 1) {
        int v = (t >= o) ? sh[t - o] : 0;
        __syncthreads();
        sh[t] += v;
        __syncthreads();
    }
    int run = (t == 0) ? 0 : sh[t - 1];
    for (int i = 0; i < CH; i++) {
        int idx = base + i;
        if (idx < NN) { g_indptr[idx] = run; g_cursor[idx] = run; run += g_deg[idx]; }
    }
    if (t == 1023) g_indptr[NN] = sh[1023];
}

// fused: CSR scatter + fp16 B-table packing + z0/z1 frag prep
__global__ void k_fused(const int* __restrict__ ei,
                        const float* __restrict__ W1, const float* __restrict__ W2,
                        const float* __restrict__ Wout,
                        const float* __restrict__ pos, const float* __restrict__ Wenc,
                        const float* __restrict__ benc) {
    int t0 = blockIdx.x * blockDim.x + threadIdx.x;
    int gs = gridDim.x * blockDim.x;
    for (int e = t0; e < EE; e += gs) {
        int d = ei[EE + e];
        int slot = atomicAdd(&g_cursor[d], 1);
        g_csr_src[slot] = ei[e];
        g_csr_eid[slot] = e;
    }
    // B tables: B1h (49152 words), BPh (49152), B2h (24576)
    for (int t = t0; t < 122880; t += gs) {
        int which, w;
        if (t < 49152) { which = 0; w = t; }
        else if (t < 98304) { which = 1; w = t - 49152; }
        else { which = 2; w = t - 98304; }
        int cb = w / 24576;
        int rem = w % 24576;
        int gks = rem >> 10;
        int r = rem & 1023;
        int nt = r >> 6;
        int r2 = r & 63;
        int lane = r2 >> 1, slot = r2 & 1;
        int n = cb * 128 + nt * 8 + (lane >> 2);
        int k0 = (gks & 7) * 16 + (lane & 3) * 2 + slot * 8;
        int term = gks >> 3;   // 0,1 = hi ; 2 = lo
        float v0, v1;
        if (which == 0) {
            v0 = (n < 128) ? W1[(128 + k0) * 128 + n] : W2[(128 + k0) * 128 + (n - 128)];
            v1 = (n < 128) ? W1[(129 + k0) * 128 + n] : W2[(129 + k0) * 128 + (n - 128)];
        } else if (which == 1) {
            v0 = (n < 128) ? W1[k0 * 128 + n] : W2[k0 * 128 + (n - 128)];
            v1 = (n < 128) ? W1[(k0 + 1) * 128 + n] : W2[(k0 + 1) * 128 + (n - 128)];
        } else {
            v0 = Wout[k0 * 128 + n];
            v1 = Wout[(k0 + 1) * 128 + n];
        }
        uint32_t word;
        if (term < 2) word = pk2h(v0, v1);
        else          word = pk2h(v0 - hi16(v0), v1 - hi16(v1));
        if (which == 0) g_B1h[w] = word;
        else if (which == 1) g_BPh[w] = word;
        else g_B2h[w] = word;
    }
    // z0 / z1 fragment prep
    for (int t = t0; t < NN * 32; t += gs) {
        int v = t >> 5, c0 = (t & 31) << 2;
        float p = pos[v];
        float4 w0 = *(const float4*)(Wenc + c0);
        float4 w1 = *(const float4*)(Wenc + 128 + c0);
        float4 b = *(const float4*)(benc + c0);
        int base = (v >> 7) * FRAGH;
        int rv = v & 127;
        int i0 = base + fidxh(rv, c0);
        int i1 = base + fidxh(rv, c0 + 2);
#pragma unroll
        for (int rr = 0; rr < 2; rr++) {
            float rf = (float)rr;
            float z0 = fmaxf(fmaf(p, w0.x, fmaf(rf, w1.x, b.x)), 0.0f);
            float z1 = fmaxf(fmaf(p, w0.y, fmaf(rf, w1.y, b.y)), 0.0f);
            float z2 = fmaxf(fmaf(p, w0.z, fmaf(rf, w1.z, b.z)), 0.0f);
            float z3 = fmaxf(fmaf(p, w0.w, fmaf(rf, w1.w, b.w)), 0.0f);
            uint32_t* dh = rr ? g_Ghf : g_Ahf;
            uint32_t* dl = rr ? g_Glf : g_Alf;
            dh[i0] = pk2h(z0, z1);
            dl[i0] = pk2h(z0 - hi16(z0), z1 - hi16(z1));
            dh[i1] = pk2h(z2, z3);
            dl[i1] = pk2h(z2 - hi16(z2), z3 - hi16(z3));
        }
    }
}

// ---------------- fp16-split GEMM tile (128 rows x 128 cols, K_ext = 384) ----------------
// MODE 0: raw fp32 -> Cout (stride 256, col offset cb*128)
// MODE 1: acc + P_sel(g_mx>=0.4) -> g_y
// MODE 2: relu(acc+bias) -> h-frag (g_Ahf/g_Alf) + fused decoder gemv -> g_a1/g_a2
template <int MODE>
__device__ __forceinline__ void gemm_tile(
    float* smem, int mb, int cb,
    const uint32_t* __restrict__ Ah, const uint32_t* __restrict__ Al,
    const uint32_t* __restrict__ Bh, float* __restrict__ Cout,
    const float* __restrict__ bias, const float* __restrict__ Wdec)
{
    const int tid = threadIdx.x, lane = tid & 31, wid = tid >> 5;
    const int wm = wid & 1, wn = wid >> 1;
    const uint32_t sbase = smem_u32(smem);
    float acc[4][4][4];
#pragma unroll
    for (int i = 0; i < 4; i++)
#pragma unroll
        for (int j = 0; j < 4; j++)
#pragma unroll
            for (int q = 0; q < 4; q++) acc[i][j][q] = 0.0f;

    auto stage = [&](int c, int buf) {
        const uint32_t* As = (((c >> 1) == 1) ? Al : Ah) + mb * FRAGH + (c & 1) * 4096;
        const uint32_t* Bs = Bh + cb * 24576 + c * 4096;
        uint32_t da = sbase + buf * 32768;
        uint32_t db = da + 16384;
#pragma unroll
        for (int i = 0; i < 4; i++) {
            int f = tid + 256 * i;
            cpasync16(da + f * 16, As + f * 4);
            cpasync16(db + f * 16, Bs + f * 4);
        }
    };

    stage(0, 0);
    asm volatile("cp.async.commit_group;");
    for (int c = 0; c < 6; c++) {
        int buf = c & 1;
        if (c < 5) {
            stage(c + 1, buf ^ 1);
            asm volatile("cp.async.commit_group;");
            asm volatile("cp.async.wait_group 1;");
        } else {
            asm volatile("cp.async.wait_group 0;");
        }
        __syncthreads();
        const uint32_t* Ab = (const uint32_t*)smem + buf * 8192;
        const uint32_t* Bb = Ab + 4096;
#pragma unroll
        for (int ks = 0; ks < 4; ks++) {
            uint4 a[4];
            uint2 b[4];
#pragma unroll
            for (int mt = 0; mt < 4; mt++)
                a[mt] = *(const uint4*)(Ab + ((ks * 8 + wm * 4 + mt) * 32 + lane) * 4);
#pragma unroll
            for (int nt = 0; nt < 4; nt++)
                b[nt] = *(const uint2*)(Bb + ((ks * 16 + wn * 4 + nt) * 32 + lane) * 2);
#pragma unroll
            for (int mt = 0; mt < 4; mt++)
#pragma unroll
                for (int nt = 0; nt < 4; nt++)
                    mma_f16(acc[mt][nt], (const uint32_t*)&a[mt], (const uint32_t*)&b[nt]);
        }
        __syncthreads();
    }

    const int row0 = mb * 128, colofs = cb * 128;
    float s1r[8], s2r[8];
#pragma unroll
    for (int i = 0; i < 8; i++) { s1r[i] = 0.0f; s2r[i] = 0.0f; }

#pragma unroll
    for (int mt = 0; mt < 4; mt++) {
        int rva = wm * 64 + mt * 16 + (lane >> 2);
        int rvb = rva + 8;
        int ga = row0 + rva, gb = row0 + rvb;
        const float *Pa = nullptr, *Pb = nullptr;
        if (MODE == 1) {
            if (ga < NN) Pa = (g_mx[ga] >= 0.4f) ? g_P1 : g_P0;
            if (gb < NN) Pb = (g_mx[gb] >= 0.4f) ? g_P1 : g_P0;
        }
#pragma unroll
        for (int nt = 0; nt < 4; nt++) {
            int col = wn * 32 + nt * 8 + ((lane & 3) << 1);
            float c0 = acc[mt][nt][0], c1 = acc[mt][nt][1];
            float c2 = acc[mt][nt][2], c3 = acc[mt][nt][3];
            if (MODE == 0) {
                if (ga < NN) { float2 v = {c0, c1}; *(float2*)(Cout + (size_t)ga * 256 + colofs + col) = v; }
                if (gb < NN) { float2 v = {c2, c3}; *(float2*)(Cout + (size_t)gb * 256 + colofs + col) = v; }
            } else if (MODE == 1) {
                if (ga < NN) {
                    float2 pv = *(const float2*)(Pa + (size_t)ga * 256 + colofs + col);
                    float2 v = {c0 + pv.x, c1 + pv.y};
                    *(float2*)(g_y + (size_t)ga * 256 + colofs + col) = v;
                }
                if (gb < NN) {
                    float2 pv = *(const float2*)(Pb + (size_t)gb * 256 + colofs + col);
                    float2 v = {c2 + pv.x, c3 + pv.y};
                    *(float2*)(g_y + (size_t)gb * 256 + colofs + col) = v;
                }
            } else {
                float b0 = bias[col], b1 = bias[col + 1];
                float w10 = Wdec[col], w11 = Wdec[col + 1];
                float w20 = Wdec[128 + col], w21 = Wdec[128 + col + 1];
                float v0 = fmaxf(c0 + b0, 0.0f), v1 = fmaxf(c1 + b1, 0.0f);
                float v2 = fmaxf(c2 + b0, 0.0f), v3 = fmaxf(c3 + b1, 0.0f);
                s1r[mt * 2 + 0] += v0 * w10 + v1 * w11;
                s2r[mt * 2 + 0] += v0 * w20 + v1 * w21;
                s1r[mt * 2 + 1] += v2 * w10 + v3 * w11;
                s2r[mt * 2 + 1] += v2 * w20 + v3 * w21;
                if (ga < NN) {
                    int i0 = mb * FRAGH + fidxh(rva, col);
                    g_Ahf[i0] = pk2h(v0, v1);
                    g_Alf[i0] = pk2h(v0 - hi16(v0), v1 - hi16(v1));
                }
                if (gb < NN) {
                    int i0 = mb * FRAGH + fidxh(rvb, col);
                    g_Ahf[i0] = pk2h(v2, v3);
                    g_Alf[i0] = pk2h(v2 - hi16(v2), v3 - hi16(v3));
                }
            }
        }
    }
    if (MODE == 2) {
        float* red = smem;  // 128*16*2 floats = 16KB
        int t3 = lane & 3;
#pragma unroll
        for (int mt = 0; mt < 4; mt++)
#pragma unroll
            for (int hf = 0; hf < 2; hf++) {
                int rl = wm * 64 + mt * 16 + (lane >> 2) + hf * 8;
                red[rl * 16 + wn * 4 + t3] = s1r[mt * 2 + hf];
                red[2048 + rl * 16 + wn * 4 + t3] = s2r[mt * 2 + hf];
            }
        __syncthreads();
        if (tid < 128) {
            int ga = row0 + tid;
            if (ga < NN) {
                float a = 0.0f, b = 0.0f;
#pragma unroll
                for (int q = 0; q < 16; q++) { a += red[tid * 16 + q]; b += red[2048 + tid * 16 + q]; }
                g_a1[ga] = a;
                g_a2[ga] = b;
            }
        }
        __syncthreads();
    }
}

// one launch: P0 (blocks 0..2*MBK-1, A = z0-frag) and P1 (blocks 2*MBK.., A = z1-frag)
__global__ __launch_bounds__(256) void k_setupgemm() {
    extern __shared__ float smem[];
    int b = blockIdx.x;
    if (b < 2 * MBK)
        gemm_tile<0>(smem, b >> 1, b & 1, g_Ahf, g_Alf, g_BPh, g_P0, nullptr, nullptr);
    else {
        b -= 2 * MBK;
        gemm_tile<0>(smem, b >> 1, b & 1, g_Ghf, g_Glf, g_BPh, g_P1, nullptr, nullptr);
    }
}
__global__ __launch_bounds__(256) void k_gemm1() {
    extern __shared__ float smem[];
    gemm_tile<1>(smem, blockIdx.x, blockIdx.y, g_Ahf, g_Alf, g_B1h, nullptr, nullptr, nullptr);
}
__global__ __launch_bounds__(256) void k_gemm2(const float* __restrict__ bout,
                                               const float* __restrict__ Wdec) {
    extern __shared__ float smem[];
    gemm_tile<2>(smem, blockIdx.x, 0, g_Ghf, g_Glf, g_B2h, nullptr, bout, Wdec);
}

// ---------------- iteration kernels ----------------
__global__ void k_ycopy(const float* __restrict__ sflag) {
    int t = blockIdx.x * blockDim.x + threadIdx.x;
    if (t >= NN * 64) return;
    int v = t >> 6, q = (t & 63) * 4;
    const float* P = (sflag[v] > 0.5f) ? g_P1 : g_P0;
    *(float4*)(g_y + (size_t)v * 256 + q) = *(const float4*)(P + (size_t)v * 256 + q);
}

// per-dst segment max; relu(max + y2 + b); write agg-frag hi/lo; zero mx
__global__ void k_segmax(const float* __restrict__ bmsg) {
    int w = (blockIdx.x * blockDim.x + threadIdx.x) >> 5;
    int lane = threadIdx.x & 31;
    if (w >= NN) return;
    int beg = g_indptr[w], end = g_indptr[w + 1];
    float4 acc = make_float4(-INFINITY, -INFINITY, -INFINITY, -INFINITY);
    for (int j = beg; j < end; j++) {
        int sv = g_csr_src[j];
        float4 v = *(const float4*)(g_y + (size_t)sv * 256 + lane * 4);
        acc.x = fmaxf(acc.x, v.x); acc.y = fmaxf(acc.y, v.y);
        acc.z = fmaxf(acc.z, v.z); acc.w = fmaxf(acc.w, v.w);
    }
    float o[4];
    if (end > beg) {
        float4 y2 = *(const float4*)(g_y + (size_t)w * 256 + 128 + lane * 4);
        float4 b = *(const float4*)(bmsg + lane * 4);
        o[0] = fmaxf(acc.x + y2.x + b.x, 0.0f);
        o[1] = fmaxf(acc.y + y2.y + b.y, 0.0f);
        o[2] = fmaxf(acc.z + y2.z + b.z, 0.0f);
        o[3] = fmaxf(acc.w + y2.w + b.w, 0.0f);
    } else {
        o[0] = o[1] = o[2] = o[3] = 0.0f;
    }
    int base = (w >> 7) * FRAGH;
    int rv = w & 127, c0 = lane << 2;
    int i0 = base + fidxh(rv, c0), i1 = base + fidxh(rv, c0 + 2);
    g_Ghf[i0] = pk2h(o[0], o[1]);
    g_Glf[i0] = pk2h(o[0] - hi16(o[0]), o[1] - hi16(o[1]));
    g_Ghf[i1] = pk2h(o[2], o[3]);
    g_Glf[i1] = pk2h(o[2] - hi16(o[2]), o[3] - hi16(o[3]));
    if (lane == 0) g_mx[w] = 0.0f;
}

__global__ void k_alpha(const int* __restrict__ ei, const float* __restrict__ bdec,
                        float* __restrict__ out, int it) {
    int e = blockIdx.x * blockDim.x + threadIdx.x;
    if (e >= EE) return;
    int sv = ei[e], dv = ei[EE + e];
    float t = g_a1[sv] + g_a2[dv] + bdec[0];
    float al = 1.0f / (1.0f + expf(-t));
    out[(size_t)it * EE + e] = al;
    atomicMax((int*)&g_mx[sv], __float_as_int(al));
    atomicMax((int*)&g_mx[dv], __float_as_int(al));
}

__global__ void k_final(const float* __restrict__ bdec, float* __restrict__ out) {
    int w = (blockIdx.x * blockDim.x + threadIdx.x) >> 5;
    int lane = threadIdx.x & 31;
    if (w >= NN) return;
    if (lane == 0) out[(size_t)10 * EE + w] = (g_mx[w] >= 0.4f) ? 1.0f : 0.0f;
    int beg = g_indptr[w], end = g_indptr[w + 1];
    float bd = bdec[0];
    float a2v = g_a2[w];
    float ba = -1.0f;
    int beid = 0x7FFFFFFF, bsrc = w;
    for (int j = beg + lane; j < end; j += 32) {
        int sv = g_csr_src[j], eid = g_csr_eid[j];
        float t = g_a1[sv] + a2v + bd;
        float al = 1.0f / (1.0f + expf(-t));
        if (al > ba || (al == ba && eid < beid)) { ba = al; beid = eid; bsrc = sv; }
    }
#pragma unroll
    for (int o = 16; o; o >>= 1) {
        float oa = __shfl_xor_sync(0xFFFFFFFFu, ba, o);
        int oe = __shfl_xor_sync(0xFFFFFFFFu, beid, o);
        int os = __shfl_xor_sync(0xFFFFFFFFu, bsrc, o);
        if (oa > ba || (oa == ba && oe < beid)) { ba = oa; beid = oe; bsrc = os; }
    }
    if (lane == 0) out[(size_t)10 * EE + NN + w] = (float)((end > beg) ? bsrc : w);
}

// ---------------- host ----------------
extern "C" void kernel_launch(void* const* d_in, const int* in_sizes, int n_in,
                              void* d_out, int out_size) {
    const float* pos  = (const float*)d_in[0];
    const float* s    = (const float*)d_in[1];
    const int*   ei   = (const int*)d_in[2];
    const float* Wenc = (const float*)d_in[3];
    const float* benc = (const float*)d_in[4];
    const float* W1   = (const float*)d_in[5];
    const float* W2   = (const float*)d_in[6];
    const float* bmsg = (const float*)d_in[7];
    const float* Wout = (const float*)d_in[8];
    const float* bout = (const float*)d_in[9];
    const float* Wdec = (const float*)d_in[10];
    const float* bdec = (const float*)d_in[11];
    float* out = (float*)d_out;

    const int SMEM = 65536;
    cudaFuncSetAttribute(k_setupgemm, cudaFuncAttributeMaxDynamicSharedMemorySize, SMEM);
    cudaFuncSetAttribute(k_gemm1, cudaFuncAttributeMaxDynamicSharedMemorySize, SMEM);
    cudaFuncSetAttribute(k_gemm2, cudaFuncAttributeMaxDynamicSharedMemorySize, SMEM);

    const int TB = 256;
    k_init<<<(NN + TB - 1) / TB, TB>>>();
    k_hist<<<(EE + TB - 1) / TB, TB>>>(ei);
    k_scan<<<1, 1024>>>();
    k_fused<<<1024, TB>>>(ei, W1, W2, Wout, pos, Wenc, benc);
    k_setupgemm<<<4 * MBK, TB, SMEM>>>();

    for (int it = 0; it < ITERS; it++) {
        if (it == 0)
            k_ycopy<<<(NN * 64 + TB - 1) / TB, TB>>>(s);
        else
            k_gemm1<<<dim3(MBK, 2), TB, SMEM>>>();
        k_segmax<<<(NN + 7) / 8, TB>>>(bmsg);
        k_gemm2<<<MBK, TB, SMEM>>>(bout, Wdec);
        k_alpha<<<(EE + TB - 1) / TB, TB>>>(ei, bdec, out, it);
    }
    k_final<<<(NN + 7) / 8, TB>>>(bdec, out);
}